// round 16
// baseline (speedup 1.0000x reference)
#include <cuda_runtime.h>
#include <cuda_bf16.h>

#define NROWS 131072
#define GCOLS 512
#define FDIM  256
#define HDIM  128
#define KDIM  64
#define NDOM  8

#define TM      64                 // rows per tile
#define NTILES  (NROWS / TM)       // 2048

#define K1PAD 272                  // GEMM1 K padded: 259 -> 272 (17 k16 steps)
#define XS_STRIDE 280              // bf16 stride (140 b32, conflict-free frags)
#define HS_STRIDE 136              // bf16 stride (68 b32)
#define ZS_STRIDE 68               // f32 stride (17 float4 / row)

#define NTHREADS 384               // 8 consumer warps + 4 producer warps

// ---------------- device scratch (no allocations allowed) ----------------
__device__ __align__(16) __nv_bfloat16 g_w1t[HDIM * XS_STRIDE];   // [n][k] = W1[k][n]
__device__ __align__(16) __nv_bfloat16 g_w2t[KDIM * HS_STRIDE];   // [n][k] = W2[k][n]

// ---------------- smem layout (bytes) ----------------
#define SM_W1   0                         // 128*280*2 = 71680
#define SM_W2   71680                     // 64*136*2  = 17408
#define SM_HS   89088                     // 64*136*2  = 17408
#define SM_XS0  106496                    // 64*280*2  = 35840
#define SM_XS1  142336                    // 35840
#define SM_ZS0  178176                    // 64*68*4   = 17408
#define SM_ZS1  195584                    // 17408
#define SM_B1   212992                    // 512
#define SM_B2   213504                    // 256
#define SM_DOM0 213760                    // 256
#define SM_DOM1 214016                    // 256
#define SM_ALP  214272                    // 32
#define SMEM_BYTES 214304

// named barriers (counts: producer 128, consumer 256, total 384)
// 2/3: produced[0/1]  (producer arrives, consumer syncs)
// 4/5: consumed[0/1]  (consumer arrives, producer syncs)
// 6:   consumer-internal (256)
__device__ __forceinline__ void bar_sync_r(int id, int cnt) {
    asm volatile("bar.sync %0, %1;" :: "r"(id), "r"(cnt) : "memory");
}
__device__ __forceinline__ void bar_arrive_r(int id, int cnt) {
    asm volatile("bar.arrive %0, %1;" :: "r"(id), "r"(cnt) : "memory");
}
#define BAR_C_INT() asm volatile("bar.sync 6, 256;" ::: "memory")

// m16n8k16 row.col bf16 -> f32 accumulate
__device__ __forceinline__ void mma_bf16(float (&c)[4], const unsigned (&a)[4],
                                         unsigned b0, unsigned b1) {
    asm volatile(
        "mma.sync.aligned.m16n8k16.row.col.f32.bf16.bf16.f32 "
        "{%0,%1,%2,%3}, {%4,%5,%6,%7}, {%8,%9}, {%0,%1,%2,%3};\n"
        : "+f"(c[0]), "+f"(c[1]), "+f"(c[2]), "+f"(c[3])
        : "r"(a[0]), "r"(a[1]), "r"(a[2]), "r"(a[3]), "r"(b0), "r"(b1));
}

// ---------------- prep: transpose + bf16-convert weights ----------------
__global__ void prep_kernel(const float* __restrict__ W1, const float* __restrict__ W2) {
    int i = blockIdx.x * blockDim.x + threadIdx.x;
    const int tot1 = HDIM * XS_STRIDE;
    if (i < tot1) {
        int n = i / XS_STRIDE, k = i - n * XS_STRIDE;
        float v = (k < FDIM + 3) ? W1[k * HDIM + n] : 0.f;
        g_w1t[i] = __float2bfloat16(v);
    } else {
        int j = i - tot1;
        if (j < KDIM * HS_STRIDE) {
            int n = j / HS_STRIDE, k = j - n * HS_STRIDE;
            float v = (k < HDIM) ? W2[k * KDIM + n] : 0.f;
            g_w2t[j] = __float2bfloat16(v);
        }
    }
}

// ---------------- persistent pipelined kernel ----------------
__global__ void __launch_bounds__(NTHREADS, 1)
fused_kernel(const float* __restrict__ z, const float* __restrict__ feats,
             const float* __restrict__ b1, const float* __restrict__ b2,
             const float* __restrict__ alphas, const int* __restrict__ dom,
             float* __restrict__ out) {
    extern __shared__ __align__(16) char smem[];
    __nv_bfloat16* w1s = (__nv_bfloat16*)(smem + SM_W1);
    __nv_bfloat16* w2s = (__nv_bfloat16*)(smem + SM_W2);
    __nv_bfloat16* hs  = (__nv_bfloat16*)(smem + SM_HS);
    float* b1s = (float*)(smem + SM_B1);
    float* b2s = (float*)(smem + SM_B2);
    float* alp = (float*)(smem + SM_ALP);

    __nv_bfloat16* xsb[2] = { (__nv_bfloat16*)(smem + SM_XS0), (__nv_bfloat16*)(smem + SM_XS1) };
    float*         zsb[2] = { (float*)(smem + SM_ZS0), (float*)(smem + SM_ZS1) };
    int*           dmb[2] = { (int*)(smem + SM_DOM0), (int*)(smem + SM_DOM1) };

    const int tid = threadIdx.x;

    // ---- one-time prologue (all 384 threads) ----
    {
        const uint4* s1 = (const uint4*)g_w1t; uint4* d1 = (uint4*)w1s;
        #pragma unroll 4
        for (int i = tid; i < (HDIM * XS_STRIDE * 2) / 16; i += NTHREADS) d1[i] = s1[i];
        const uint4* s2 = (const uint4*)g_w2t; uint4* d2 = (uint4*)w2s;
        #pragma unroll 2
        for (int i = tid; i < (KDIM * HS_STRIDE * 2) / 16; i += NTHREADS) d2[i] = s2[i];
    }
    if (tid < HDIM) b1s[tid] = b1[tid];
    if (tid < KDIM) b2s[tid] = b2[tid];
    if (tid < NDOM) alp[tid] = alphas[tid];
    // zero xs pad cols [256,272) for both buffers (conf rewrites 256-258 per tile)
    for (int i = tid; i < 2 * TM * 16; i += NTHREADS) {
        int b = i >> 10, r = (i >> 4) & (TM - 1), c = 256 + (i & 15);
        xsb[b][r * XS_STRIDE + c] = __float2bfloat16(0.f);
    }
    __syncthreads();

    if (tid >= 256) {
        // ================= PRODUCER (4 warps, 128 threads) =================
        const int ctid = tid - 256;            // 0..127
        int it = 0;
        for (int tile = blockIdx.x; tile < NTILES; tile += gridDim.x, it++) {
            const int buf = it & 1;
            const int row0 = tile * TM;
            const float4* z4 = (const float4*)z + (size_t)row0 * (GCOLS / 4);
            float4*       o4 = (float4*)out     + (size_t)row0 * (GCOLS / 4);
            const int* dr = dom + row0;
            __nv_bfloat16* xs = xsb[buf];
            float4* zs4 = (float4*)zsb[buf];
            int* dms = dmb[buf];

            bar_sync_r(4 + buf, NTHREADS);     // consumed[buf] (pre-armed at start)

            if (ctid < TM) dms[ctid] = __ldg(dr + ctid);

            // feats -> xs[buf] (bf16)
            {
                const float4* f4 = (const float4*)feats + (size_t)row0 * (FDIM / 4);
                #pragma unroll 8
                for (int i = ctid; i < TM * (FDIM / 4); i += 128) {
                    int r = i >> 6, c4 = i & 63;
                    float4 v = f4[(size_t)r * (FDIM / 4) + c4];
                    __nv_bfloat162 p0 = __floats2bfloat162_rn(v.x, v.y);
                    __nv_bfloat162 p1 = __floats2bfloat162_rn(v.z, v.w);
                    *(__nv_bfloat162*)(xs + r * XS_STRIDE + c4 * 4)     = p0;
                    *(__nv_bfloat162*)(xs + r * XS_STRIDE + c4 * 4 + 2) = p1;
                }
            }
            // owned slice -> zs[buf]
            #pragma unroll 8
            for (int i = ctid; i < TM * 16; i += 128) {
                int r = i >> 4, qd = i & 15;
                int d = __ldg(dr + r);
                zs4[r * (ZS_STRIDE / 4) + qd] = z4[r * 128 + (d << 4) + qd];
            }
            bar_arrive_r(2 + buf, NTHREADS);   // produced[buf]

            // non-owned passthrough z -> out (overlaps consumer compute)
            {
                const int cb = ctid >> 4;      // 16-f4 block of this column
                #pragma unroll 8
                for (int r = 0; r < TM; r++) {
                    int d = __ldg(dr + r);
                    if (cb != d) o4[r * 128 + ctid] = z4[r * 128 + ctid];
                }
            }
        }
        return;
    }

    // ================= CONSUMER (8 warps, 256 threads) =================
    const int lane = tid & 31, wid = tid >> 5;
    const int g = lane >> 2, t = lane & 3;
    const int wm = wid & 1, wn = wid >> 1;     // 2(m) x 4(n) warp grid

    // pre-arm both consumed barriers so producer's first two waits pass
    bar_arrive_r(4, NTHREADS);
    bar_arrive_r(5, NTHREADS);

    int it = 0;
    for (int tile = blockIdx.x; tile < NTILES; tile += gridDim.x, it++) {
        const int buf = it & 1;
        const int row0 = tile * TM;
        float4* o4 = (float4*)out + (size_t)row0 * (GCOLS / 4);
        __nv_bfloat16* xs = xsb[buf];
        float* zs = zsb[buf];
        float4* zs4 = (float4*)zs;
        int* dms = dmb[buf];

        bar_sync_r(2 + buf, NTHREADS);         // produced[buf]

        // --- conf stats: one thread per row ---
        if (tid < TM) {
            const float4* vr4 = (const float4*)(zs + tid * ZS_STRIDE);
            float v[64];
            #pragma unroll
            for (int i = 0; i < 16; i++) {
                float4 tv = vr4[i];
                v[4*i] = tv.x; v[4*i+1] = tv.y; v[4*i+2] = tv.z; v[4*i+3] = tv.w;
            }
            float m1 = -3.4e38f, m2 = -3.4e38f;
            #pragma unroll
            for (int i = 0; i < 64; i++) {
                float x = v[i];
                if (x > m1) { m2 = m1; m1 = x; }
                else if (x > m2) { m2 = x; }
            }
            float S = 0.f, T = 0.f;
            #pragma unroll
            for (int i = 0; i < 64; i++) {
                float e = __expf(v[i] - m1);
                S += e;
                T += (v[i] - m1) * e;
            }
            float pmax = 1.f / S;
            float ent  = __logf(S) - T * pmax;
            float marg = (1.f - __expf(m2 - m1)) * pmax;
            __nv_bfloat16* xr = xs + tid * XS_STRIDE;
            xr[256] = __float2bfloat16(pmax);
            xr[257] = __float2bfloat16(ent);
            xr[258] = __float2bfloat16(marg);
        }
        BAR_C_INT();                           // xs complete

        // ---------- GEMM1: [64 x 272] @ [272 x 128] -> h, warp tile 32x32 ----------
        {
            float c1[2][4][4];
            #pragma unroll
            for (int mi = 0; mi < 2; mi++)
                #pragma unroll
                for (int nf = 0; nf < 4; nf++)
                    #pragma unroll
                    for (int q = 0; q < 4; q++) c1[mi][nf][q] = 0.f;

            const unsigned* xs32  = (const unsigned*)xs;
            const unsigned* w1s32 = (const unsigned*)w1s;

            #pragma unroll 4
            for (int ks = 0; ks < 17; ks++) {
                const int kp = ks * 8 + t;
                unsigned a[2][4];
                #pragma unroll
                for (int mi = 0; mi < 2; mi++) {
                    int r = wm * 32 + mi * 16 + g;
                    a[mi][0] = xs32[r * 140 + kp];
                    a[mi][1] = xs32[(r + 8) * 140 + kp];
                    a[mi][2] = xs32[r * 140 + kp + 4];
                    a[mi][3] = xs32[(r + 8) * 140 + kp + 4];
                }
                #pragma unroll
                for (int nf = 0; nf < 4; nf++) {
                    int n = wn * 32 + nf * 8 + g;
                    unsigned b0 = w1s32[n * 140 + kp];
                    unsigned bb = w1s32[n * 140 + kp + 4];
                    mma_bf16(c1[0][nf], a[0], b0, bb);
                    mma_bf16(c1[1][nf], a[1], b0, bb);
                }
            }

            // bias + relu -> hs (bf16 pairs)
            unsigned* hs32 = (unsigned*)hs;
            #pragma unroll
            for (int mi = 0; mi < 2; mi++) {
                int r = wm * 32 + mi * 16 + g;
                #pragma unroll
                for (int nf = 0; nf < 4; nf++) {
                    int ncol = wn * 32 + nf * 8 + 2 * t;
                    float bb0 = b1s[ncol], bb1 = b1s[ncol + 1];
                    float h0 = fmaxf(c1[mi][nf][0] + bb0, 0.f);
                    float h1 = fmaxf(c1[mi][nf][1] + bb1, 0.f);
                    float h2 = fmaxf(c1[mi][nf][2] + bb0, 0.f);
                    float h3 = fmaxf(c1[mi][nf][3] + bb1, 0.f);
                    __nv_bfloat162 p0 = __floats2bfloat162_rn(h0, h1);
                    __nv_bfloat162 p1 = __floats2bfloat162_rn(h2, h3);
                    hs32[r * 68 + wn * 16 + nf * 4 + t]       = *(unsigned*)&p0;
                    hs32[(r + 8) * 68 + wn * 16 + nf * 4 + t] = *(unsigned*)&p1;
                }
            }
        }
        BAR_C_INT();                           // hs ready

        // ---------- GEMM2: [64 x 128] @ [128 x 64] -> dz, add into zs, warp 32x16 ----------
        {
            float c2[2][2][4];
            #pragma unroll
            for (int mi = 0; mi < 2; mi++)
                #pragma unroll
                for (int nf = 0; nf < 2; nf++)
                    #pragma unroll
                    for (int q = 0; q < 4; q++) c2[mi][nf][q] = 0.f;

            const unsigned* hs32  = (const unsigned*)hs;
            const unsigned* w2s32 = (const unsigned*)w2s;

            #pragma unroll
            for (int ks = 0; ks < 8; ks++) {
                const int kp = ks * 8 + t;
                unsigned a[2][4];
                #pragma unroll
                for (int mi = 0; mi < 2; mi++) {
                    int r = wm * 32 + mi * 16 + g;
                    a[mi][0] = hs32[r * 68 + kp];
                    a[mi][1] = hs32[(r + 8) * 68 + kp];
                    a[mi][2] = hs32[r * 68 + kp + 4];
                    a[mi][3] = hs32[(r + 8) * 68 + kp + 4];
                }
                #pragma unroll
                for (int nf = 0; nf < 2; nf++) {
                    int n = wn * 16 + nf * 8 + g;
                    unsigned b0 = w2s32[n * 68 + kp];
                    unsigned bb = w2s32[n * 68 + kp + 4];
                    mma_bf16(c2[0][nf], a[0], b0, bb);
                    mma_bf16(c2[1][nf], a[1], b0, bb);
                }
            }

            // epilogue: zs += (c2 + b2) * alpha(domain)
            #pragma unroll
            for (int mi = 0; mi < 2; mi++) {
                int rl = wm * 32 + mi * 16 + g;
                float al0 = alp[dms[rl]];
                float al1 = alp[dms[rl + 8]];
                #pragma unroll
                for (int nf = 0; nf < 2; nf++) {
                    int col = wn * 16 + nf * 8 + 2 * t;
                    float bb0 = b2s[col], bb1 = b2s[col + 1];
                    float2* p0 = (float2*)&zs[rl * ZS_STRIDE + col];
                    float2* p1 = (float2*)&zs[(rl + 8) * ZS_STRIDE + col];
                    float2 v0 = *p0, v1 = *p1;
                    v0.x += (c2[mi][nf][0] + bb0) * al0;
                    v0.y += (c2[mi][nf][1] + bb1) * al0;
                    v1.x += (c2[mi][nf][2] + bb0) * al1;
                    v1.y += (c2[mi][nf][3] + bb1) * al1;
                    *p0 = v0; *p1 = v1;
                }
            }
        }
        BAR_C_INT();                           // zs final

        // --- owned-slice writeback (256B contiguous per row) ---
        #pragma unroll 4
        for (int i = tid; i < TM * 16; i += 256) {
            int r = i >> 4, qd = i & 15;
            o4[r * 128 + (dms[r] << 4) + qd] = zs4[r * (ZS_STRIDE / 4) + qd];
        }
        bar_arrive_r(4 + buf, NTHREADS);       // consumed[buf]
    }
}

extern "C" void kernel_launch(void* const* d_in, const int* in_sizes, int n_in,
                              void* d_out, int out_size) {
    const float* z      = (const float*)d_in[0];
    const float* feats  = (const float*)d_in[1];
    const float* W1     = (const float*)d_in[2];
    const float* b1     = (const float*)d_in[3];
    const float* W2     = (const float*)d_in[4];
    const float* b2     = (const float*)d_in[5];
    const float* alphas = (const float*)d_in[6];
    const int*   dom    = (const int*)d_in[7];
    float* out = (float*)d_out;

    cudaFuncSetAttribute(fused_kernel, cudaFuncAttributeMaxDynamicSharedMemorySize,
                         SMEM_BYTES);

    int dev = 0, nsm = 148;
    cudaGetDevice(&dev);
    cudaDeviceGetAttribute(&nsm, cudaDevAttrMultiProcessorCount, dev);
    if (nsm <= 0 || nsm > NTILES) nsm = 148;

    const int preptot = HDIM * XS_STRIDE + KDIM * HS_STRIDE;
    prep_kernel<<<(preptot + 255) / 256, 256>>>(W1, W2);
    fused_kernel<<<nsm, NTHREADS, SMEM_BYTES>>>(z, feats, b1, b2, alphas, dom, out);
}

// round 17
// speedup vs baseline: 1.6080x; 1.6080x over previous
#include <cuda_runtime.h>
#include <cuda_bf16.h>

#define NROWS 131072
#define GCOLS 512
#define FDIM  256
#define HDIM  128
#define KDIM  64
#define NDOM  8

#define TM      128
#define NTILES  (NROWS / TM)       // 1024

#define K1PAD 272                  // GEMM1 K padded: 259 -> 272 (17 k16 steps)
#define XS_STRIDE 280              // bf16 stride (140 b32, conflict-free frags)
#define HS_STRIDE 136              // bf16 stride (68 b32)
#define ZS_STRIDE 68               // f32 stride (17 float4 / row)

#define NTHREADS 512               // 256 consumer + 256 producer

// ---------------- device scratch (no allocations allowed) ----------------
__device__ __align__(16) __nv_bfloat16 g_w1t[HDIM * XS_STRIDE];   // [n][k] = W1[k][n]
__device__ __align__(16) __nv_bfloat16 g_w2t[KDIM * HS_STRIDE];   // [n][k] = W2[k][n]

// ---------------- smem layout (bytes) ----------------
#define SM_XS   0                          // 128*280*2 = 71680
#define SM_W1   71680                      // 71680
#define SM_HS   143360                     // 128*136*2 = 34816
#define SM_W2   178176                     // 64*136*2  = 17408
#define SM_ZS   195584                     // 128*68*4  = 34816
#define SM_B1   230400                     // 512
#define SM_B2   230912                     // 256
#define SM_DOM  231168                     // 512
#define SM_ALP  231680                     // 32
#define SMEM_BYTES 231712

// named barriers (all full-block count 512 except consumer-internal 256)
// id 2: zs+dms ready   (producer arrives 256, consumer syncs 256)
// id 5: xs ready       (producer arrives 256, consumer syncs 256)
// id 3: tile consumed  (consumer arrives 256, producer syncs 256)
// id 4: consumer-internal (256)
__device__ __forceinline__ void bar_sync_id(int id, int cnt) {
    asm volatile("bar.sync %0, %1;" :: "r"(id), "r"(cnt) : "memory");
}
__device__ __forceinline__ void bar_arrive_id(int id, int cnt) {
    asm volatile("bar.arrive %0, %1;" :: "r"(id), "r"(cnt) : "memory");
}
#define BAR_C_INT() asm volatile("bar.sync 4, 256;" ::: "memory")

// m16n8k16 row.col bf16 -> f32 accumulate
__device__ __forceinline__ void mma_bf16(float (&c)[4], const unsigned (&a)[4],
                                         unsigned b0, unsigned b1) {
    asm volatile(
        "mma.sync.aligned.m16n8k16.row.col.f32.bf16.bf16.f32 "
        "{%0,%1,%2,%3}, {%4,%5,%6,%7}, {%8,%9}, {%0,%1,%2,%3};\n"
        : "+f"(c[0]), "+f"(c[1]), "+f"(c[2]), "+f"(c[3])
        : "r"(a[0]), "r"(a[1]), "r"(a[2]), "r"(a[3]), "r"(b0), "r"(b1));
}

// ---------------- prep: transpose + bf16-convert weights ----------------
__global__ void prep_kernel(const float* __restrict__ W1, const float* __restrict__ W2) {
    int i = blockIdx.x * blockDim.x + threadIdx.x;
    const int tot1 = HDIM * XS_STRIDE;
    if (i < tot1) {
        int n = i / XS_STRIDE, k = i - n * XS_STRIDE;
        float v = (k < FDIM + 3) ? W1[k * HDIM + n] : 0.f;
        g_w1t[i] = __float2bfloat16(v);
    } else {
        int j = i - tot1;
        if (j < KDIM * HS_STRIDE) {
            int n = j / HS_STRIDE, k = j - n * HS_STRIDE;
            float v = (k < HDIM) ? W2[k * KDIM + n] : 0.f;
            g_w2t[j] = __float2bfloat16(v);
        }
    }
}

// ---------------- persistent producer/consumer kernel ----------------
__global__ void __launch_bounds__(NTHREADS, 1)
fused_kernel(const float* __restrict__ z, const float* __restrict__ feats,
             const float* __restrict__ b1, const float* __restrict__ b2,
             const float* __restrict__ alphas, const int* __restrict__ dom,
             float* __restrict__ out) {
    extern __shared__ __align__(16) char smem[];
    __nv_bfloat16* xs  = (__nv_bfloat16*)(smem + SM_XS);
    __nv_bfloat16* w1s = (__nv_bfloat16*)(smem + SM_W1);
    __nv_bfloat16* hs  = (__nv_bfloat16*)(smem + SM_HS);
    __nv_bfloat16* w2s = (__nv_bfloat16*)(smem + SM_W2);
    float* zs  = (float*)(smem + SM_ZS);
    float* b1s = (float*)(smem + SM_B1);
    float* b2s = (float*)(smem + SM_B2);
    int*   dms = (int*)(smem + SM_DOM);
    float* alp = (float*)(smem + SM_ALP);

    const int tid = threadIdx.x;

    // ---- one-time prologue (all 512 threads) ----
    {
        const uint4* s1 = (const uint4*)g_w1t; uint4* d1 = (uint4*)w1s;
        #pragma unroll 4
        for (int i = tid; i < (HDIM * XS_STRIDE * 2) / 16; i += NTHREADS) d1[i] = s1[i];
        const uint4* s2 = (const uint4*)g_w2t; uint4* d2 = (uint4*)w2s;
        #pragma unroll 2
        for (int i = tid; i < (KDIM * HS_STRIDE * 2) / 16; i += NTHREADS) d2[i] = s2[i];
    }
    if (tid < HDIM) b1s[tid] = b1[tid];
    if (tid < KDIM) b2s[tid] = b2[tid];
    if (tid < NDOM) alp[tid] = alphas[tid];
    // zero xs pad cols [256,272) once (conf rewrites 256-258 per tile, feats 0-255)
    for (int i = tid; i < TM * 16; i += NTHREADS) {
        int r = i >> 4, c = 256 + (i & 15);
        xs[r * XS_STRIDE + c] = __float2bfloat16(0.f);
    }
    __syncthreads();

    if (tid >= 256) {
        // ================= PRODUCER (8 warps, 256 threads) =================
        const int ctid = tid - 256;            // 0..255
        for (int tile = blockIdx.x; tile < NTILES; tile += gridDim.x) {
            const int row0 = tile * TM;
            const float4* z4 = (const float4*)z + (size_t)row0 * (GCOLS / 4);
            float4*       o4 = (float4*)out     + (size_t)row0 * (GCOLS / 4);
            const int* dr = dom + row0;
            float4* zs4 = (float4*)zs;

            bar_sync_id(3, NTHREADS);          // tile consumed (pre-armed once)

            // dms + owned slice -> zs
            if (ctid < TM) dms[ctid] = __ldg(dr + ctid);
            #pragma unroll 8
            for (int i = ctid; i < TM * 16; i += 256) {
                int r = i >> 4, qd = i & 15;
                int d = __ldg(dr + r);
                zs4[r * (ZS_STRIDE / 4) + qd] = z4[r * 128 + (d << 4) + qd];
            }
            bar_arrive_id(2, NTHREADS);        // zs + dms ready

            // feats -> xs (bf16)
            {
                const float4* f4 = (const float4*)feats + (size_t)row0 * (FDIM / 4);
                #pragma unroll 8
                for (int i = ctid; i < TM * (FDIM / 4); i += 256) {
                    int r = i >> 6, c4 = i & 63;
                    float4 v = f4[(size_t)r * (FDIM / 4) + c4];
                    __nv_bfloat162 p0 = __floats2bfloat162_rn(v.x, v.y);
                    __nv_bfloat162 p1 = __floats2bfloat162_rn(v.z, v.w);
                    *(__nv_bfloat162*)(xs + r * XS_STRIDE + c4 * 4)     = p0;
                    *(__nv_bfloat162*)(xs + r * XS_STRIDE + c4 * 4 + 2) = p1;
                }
            }
            bar_arrive_id(5, NTHREADS);        // xs ready

            // non-owned passthrough z -> out (overlaps consumer math)
            {
                const int q  = ctid & 127;     // column f4
                const int cb = q >> 4;         // 16-f4 block of this column
                const int r0 = ctid >> 7;      // 0 or 1
                #pragma unroll 16
                for (int r = r0; r < TM; r += 2) {
                    int d = __ldg(dr + r);
                    if (cb != d) o4[r * 128 + q] = z4[r * 128 + q];
                }
            }
        }
        return;
    }

    // ================= CONSUMER (8 warps, 256 threads) =================
    const int lane = tid & 31, wid = tid >> 5;
    const int g = lane >> 2, t = lane & 3;

    bar_arrive_id(3, NTHREADS);                // pre-arm consumed

    for (int tile = blockIdx.x; tile < NTILES; tile += gridDim.x) {
        const int row0 = tile * TM;
        float4* o4 = (float4*)out + (size_t)row0 * (GCOLS / 4);
        float4* zs4 = (float4*)zs;

        bar_sync_id(2, NTHREADS);              // zs + dms ready

        // --- conf stats: one thread per row, two passes from smem ---
        if (tid < TM) {
            const float4* vr4 = (const float4*)(zs + tid * ZS_STRIDE);
            float m1 = -3.4e38f, m2 = -3.4e38f;
            #pragma unroll
            for (int i = 0; i < 16; i++) {
                float4 tv = vr4[i];
                float x;
                x = tv.x; if (x > m1) { m2 = m1; m1 = x; } else if (x > m2) m2 = x;
                x = tv.y; if (x > m1) { m2 = m1; m1 = x; } else if (x > m2) m2 = x;
                x = tv.z; if (x > m1) { m2 = m1; m1 = x; } else if (x > m2) m2 = x;
                x = tv.w; if (x > m1) { m2 = m1; m1 = x; } else if (x > m2) m2 = x;
            }
            float S = 0.f, T = 0.f;
            #pragma unroll
            for (int i = 0; i < 16; i++) {
                float4 tv = vr4[i];
                float e;
                e = __expf(tv.x - m1); S += e; T += (tv.x - m1) * e;
                e = __expf(tv.y - m1); S += e; T += (tv.y - m1) * e;
                e = __expf(tv.z - m1); S += e; T += (tv.z - m1) * e;
                e = __expf(tv.w - m1); S += e; T += (tv.w - m1) * e;
            }
            float pmax = 1.f / S;
            float ent  = __logf(S) - T * pmax;
            float marg = (1.f - __expf(m2 - m1)) * pmax;
            __nv_bfloat16* xr = xs + tid * XS_STRIDE;
            xr[256] = __float2bfloat16(pmax);
            xr[257] = __float2bfloat16(ent);
            xr[258] = __float2bfloat16(marg);
        }
        BAR_C_INT();                           // conf cols visible to all consumers
        bar_sync_id(5, NTHREADS);              // xs (feats) ready

        // ---------- GEMM1: [128 x 272] @ [272 x 128] -> h ----------
        // warps 4(m) x 2(n); n split into two halves of 32 (32-reg accumulators)
        {
            const int wm = wid & 3, wn = wid >> 2;
            const unsigned* xs32  = (const unsigned*)xs;
            const unsigned* w1s32 = (const unsigned*)w1s;
            unsigned* hs32 = (unsigned*)hs;

            #pragma unroll
            for (int nh = 0; nh < 2; nh++) {
                float c1[2][4][4];
                #pragma unroll
                for (int mi = 0; mi < 2; mi++)
                    #pragma unroll
                    for (int nf = 0; nf < 4; nf++)
                        #pragma unroll
                        for (int q = 0; q < 4; q++) c1[mi][nf][q] = 0.f;

                #pragma unroll 4
                for (int ks = 0; ks < 17; ks++) {
                    const int kp = ks * 8 + t;
                    unsigned a[2][4];
                    #pragma unroll
                    for (int mi = 0; mi < 2; mi++) {
                        int r = wm * 32 + mi * 16 + g;
                        a[mi][0] = xs32[r * 140 + kp];
                        a[mi][1] = xs32[(r + 8) * 140 + kp];
                        a[mi][2] = xs32[r * 140 + kp + 4];
                        a[mi][3] = xs32[(r + 8) * 140 + kp + 4];
                    }
                    #pragma unroll
                    for (int nf = 0; nf < 4; nf++) {
                        int n = wn * 64 + nh * 32 + nf * 8 + g;
                        unsigned b0 = w1s32[n * 140 + kp];
                        unsigned bb = w1s32[n * 140 + kp + 4];
                        mma_bf16(c1[0][nf], a[0], b0, bb);
                        mma_bf16(c1[1][nf], a[1], b0, bb);
                    }
                }

                // bias + relu -> hs (bf16 pairs)
                #pragma unroll
                for (int mi = 0; mi < 2; mi++) {
                    int r = wm * 32 + mi * 16 + g;
                    #pragma unroll
                    for (int nf = 0; nf < 4; nf++) {
                        int ncol = wn * 64 + nh * 32 + nf * 8 + 2 * t;
                        float bb0 = b1s[ncol], bb1 = b1s[ncol + 1];
                        float h0 = fmaxf(c1[mi][nf][0] + bb0, 0.f);
                        float h1 = fmaxf(c1[mi][nf][1] + bb1, 0.f);
                        float h2 = fmaxf(c1[mi][nf][2] + bb0, 0.f);
                        float h3 = fmaxf(c1[mi][nf][3] + bb1, 0.f);
                        __nv_bfloat162 p0 = __floats2bfloat162_rn(h0, h1);
                        __nv_bfloat162 p1 = __floats2bfloat162_rn(h2, h3);
                        hs32[r * 68 + wn * 32 + nh * 16 + nf * 4 + t]       = *(unsigned*)&p0;
                        hs32[(r + 8) * 68 + wn * 32 + nh * 16 + nf * 4 + t] = *(unsigned*)&p1;
                    }
                }
            }
        }
        BAR_C_INT();                           // hs ready

        // ---------- GEMM2: [128 x 128] @ [128 x 64] -> dz, add into zs ----------
        {
            const int wm = wid & 3, wn = wid >> 2;    // warp tile 32x32
            float c2[2][4][4];
            #pragma unroll
            for (int mi = 0; mi < 2; mi++)
                #pragma unroll
                for (int nf = 0; nf < 4; nf++)
                    #pragma unroll
                    for (int q = 0; q < 4; q++) c2[mi][nf][q] = 0.f;

            const unsigned* hs32  = (const unsigned*)hs;
            const unsigned* w2s32 = (const unsigned*)w2s;

            #pragma unroll
            for (int ks = 0; ks < 8; ks++) {
                const int kp = ks * 8 + t;
                unsigned a[2][4];
                #pragma unroll
                for (int mi = 0; mi < 2; mi++) {
                    int r = wm * 32 + mi * 16 + g;
                    a[mi][0] = hs32[r * 68 + kp];
                    a[mi][1] = hs32[(r + 8) * 68 + kp];
                    a[mi][2] = hs32[r * 68 + kp + 4];
                    a[mi][3] = hs32[(r + 8) * 68 + kp + 4];
                }
                #pragma unroll
                for (int nf = 0; nf < 4; nf++) {
                    int n = wn * 32 + nf * 8 + g;
                    unsigned b0 = w2s32[n * 68 + kp];
                    unsigned bb = w2s32[n * 68 + kp + 4];
                    mma_bf16(c2[0][nf], a[0], b0, bb);
                    mma_bf16(c2[1][nf], a[1], b0, bb);
                }
            }

            // epilogue: zs += (c2 + b2) * alpha(domain)
            #pragma unroll
            for (int mi = 0; mi < 2; mi++) {
                int rl = wm * 32 + mi * 16 + g;
                float al0 = alp[dms[rl]];
                float al1 = alp[dms[rl + 8]];
                #pragma unroll
                for (int nf = 0; nf < 4; nf++) {
                    int col = wn * 32 + nf * 8 + 2 * t;
                    float bb0 = b2s[col], bb1 = b2s[col + 1];
                    float2* p0 = (float2*)&zs[rl * ZS_STRIDE + col];
                    float2* p1 = (float2*)&zs[(rl + 8) * ZS_STRIDE + col];
                    float2 v0 = *p0, v1 = *p1;
                    v0.x += (c2[mi][nf][0] + bb0) * al0;
                    v0.y += (c2[mi][nf][1] + bb1) * al0;
                    v1.x += (c2[mi][nf][2] + bb0) * al1;
                    v1.y += (c2[mi][nf][3] + bb1) * al1;
                    *p0 = v0; *p1 = v1;
                }
            }
        }
        BAR_C_INT();                           // zs final

        // --- owned-slice writeback (256B contiguous per row) ---
        #pragma unroll 8
        for (int i = tid; i < TM * 16; i += 256) {
            int r = i >> 4, qd = i & 15;
            o4[r * 128 + (dms[r] << 4) + qd] = zs4[r * (ZS_STRIDE / 4) + qd];
        }
        bar_arrive_id(3, NTHREADS);            // tile consumed
    }
}

extern "C" void kernel_launch(void* const* d_in, const int* in_sizes, int n_in,
                              void* d_out, int out_size) {
    const float* z      = (const float*)d_in[0];
    const float* feats  = (const float*)d_in[1];
    const float* W1     = (const float*)d_in[2];
    const float* b1     = (const float*)d_in[3];
    const float* W2     = (const float*)d_in[4];
    const float* b2     = (const float*)d_in[5];
    const float* alphas = (const float*)d_in[6];
    const int*   dom    = (const int*)d_in[7];
    float* out = (float*)d_out;

    cudaFuncSetAttribute(fused_kernel, cudaFuncAttributeMaxDynamicSharedMemorySize,
                         SMEM_BYTES);

    int dev = 0, nsm = 148;
    cudaGetDevice(&dev);
    cudaDeviceGetAttribute(&nsm, cudaDevAttrMultiProcessorCount, dev);
    if (nsm <= 0 || nsm > NTILES) nsm = 148;

    const int preptot = HDIM * XS_STRIDE + KDIM * HS_STRIDE;
    prep_kernel<<<(preptot + 255) / 256, 256>>>(W1, W2);
    fused_kernel<<<nsm, NTHREADS, SMEM_BYTES>>>(z, feats, b1, b2, alphas, dom, out);
}